// round 1
// baseline (speedup 1.0000x reference)
#include <cuda_runtime.h>
#include <cuda_bf16.h>
#include <float.h>
#include <stdint.h>

// Problem constants
#define B        16
#define H        320
#define W        320
#define HW       (H * W)          // 102400
#define P        64
#define K_TOP    100
#define NBINS    1024
#define CAND_CAP 32768            // per-batch global candidate capacity
#define SBUF     1024             // shared sort buffer (power of 2)

// Output layout (float32, concatenated in reference tuple order):
//   coors  [B,K,2]  -> offset 0      (3200)
//   params [B,K,64] -> offset 3200   (102400)
//   scores [B,K]    -> offset 105600 (1600)
//   mask   [B,K]    -> offset 107200 (1600)
#define OFF_COORS  0
#define OFF_PARAMS 3200
#define OFF_SCORES 105600
#define OFF_MASK   107200

// Device scratch (no allocation allowed)
__device__ unsigned           g_hist[B * NBINS];
__device__ unsigned           g_cnt[B];
__device__ unsigned long long g_cand[B * CAND_CAP];

// ---------------------------------------------------------------------------
// K0: zero histogram + counters (must run each graph replay)
// ---------------------------------------------------------------------------
__global__ void k0_zero() {
    int gid = blockIdx.x * blockDim.x + threadIdx.x;
    int total = B * NBINS;
    for (int i = gid; i < total; i += gridDim.x * blockDim.x) g_hist[i] = 0;
    if (gid < B) g_cnt[gid] = 0;
}

// ---------------------------------------------------------------------------
// K1: 3x3 peak NMS + candidate collection (one thread per pixel)
// Warp covers 32 consecutive x in one row (320 % 32 == 0, rows never split).
// ---------------------------------------------------------------------------
__global__ void k1_peaks(const float* __restrict__ hms) {
    int gid  = blockIdx.x * blockDim.x + threadIdx.x;   // 0 .. B*HW-1
    int lane = threadIdx.x & 31;

    int b   = gid / HW;
    int rem = gid - b * HW;
    int y   = rem / W;
    int x   = rem - y * W;

    const float* hb = hms + b * HW;

    // Column max at x over rows y-1..y+1 (SAME padding = ignore OOB rows)
    float mid = hb[y * W + x];
    float cm  = mid;
    if (y > 0)     cm = fmaxf(cm, hb[(y - 1) * W + x]);
    if (y < H - 1) cm = fmaxf(cm, hb[(y + 1) * W + x]);

    // Horizontal 3-wide max via shuffle; warp-edge lanes load the outside column
    float lm = __shfl_up_sync(0xffffffffu, cm, 1);
    if (lane == 0) {
        lm = -FLT_MAX;
        if (x > 0) {
            lm = hb[y * W + (x - 1)];
            if (y > 0)     lm = fmaxf(lm, hb[(y - 1) * W + (x - 1)]);
            if (y < H - 1) lm = fmaxf(lm, hb[(y + 1) * W + (x - 1)]);
        }
    }
    float rm = __shfl_down_sync(0xffffffffu, cm, 1);
    if (lane == 31) {
        rm = -FLT_MAX;
        if (x < W - 1) {
            rm = hb[y * W + (x + 1)];
            if (y > 0)     rm = fmaxf(rm, hb[(y - 1) * W + (x + 1)]);
            if (y < H - 1) rm = fmaxf(rm, hb[(y + 1) * W + (x + 1)]);
        }
    }
    float wmax = fmaxf(fmaxf(lm, cm), rm);

    // Peak iff center equals the 3x3 window max; only scores > 0.5 matter.
    bool isCand = (mid >= wmax) && (mid > 0.5f);

    unsigned ballot = __ballot_sync(0xffffffffu, isCand);
    if (ballot) {
        // All lanes in a warp share the same batch b (alignment argument above).
        int leader = __ffs(ballot) - 1;
        unsigned base = 0;
        if (lane == leader) base = atomicAdd(&g_cnt[b], (unsigned)__popc(ballot));
        base = __shfl_sync(0xffffffffu, base, leader);
        if (isCand) {
            unsigned bits = __float_as_uint(mid);           // mid in (0.5, 1)
            unsigned bin;
            if (bits >= 0x3F800000u) bin = NBINS - 1;       // safety clamp
            else                     bin = (bits - 0x3F000000u) >> 13;
            atomicAdd(&g_hist[b * NBINS + bin], 1u);

            unsigned off = base + (unsigned)__popc(ballot & ((1u << lane) - 1u));
            if (off < CAND_CAP) {
                unsigned pixIdx = (unsigned)rem;            // batch-local
                unsigned long long key =
                    ((unsigned long long)bits << 32) | (unsigned)(~pixIdx);
                g_cand[b * CAND_CAP + off] = key;
            }
        }
    }
}

// ---------------------------------------------------------------------------
// K2: per batch — cutoff from histogram, filter, bitonic sort, decode, gather
// One block of 256 threads per batch.
// ---------------------------------------------------------------------------
__global__ void k2_select(const float* __restrict__ pms, float* __restrict__ out) {
    __shared__ unsigned long long s_cand[SBUF];
    __shared__ unsigned s_n;
    __shared__ unsigned s_thresh;
    __shared__ int   s_y[K_TOP];
    __shared__ int   s_x[K_TOP];
    __shared__ int   s_valid[K_TOP];

    int b   = blockIdx.x;
    int tid = threadIdx.x;

    // Init shared buffer with zero keys (sink to the end when sorted descending)
    for (int i = tid; i < SBUF; i += blockDim.x) s_cand[i] = 0ull;
    if (tid == 0) {
        s_n = 0;
        // Suffix scan from the top bin; typically terminates in a few bins.
        unsigned acc = 0;
        int cut = 0;
        for (int bin = NBINS - 1; bin >= 0; --bin) {
            acc += g_hist[b * NBINS + bin];
            if (acc >= K_TOP) { cut = bin; break; }
        }
        s_thresh = 0x3F000000u + ((unsigned)cut << 13);
    }
    __syncthreads();

    // Filter candidate list down to shared
    unsigned cnt = g_cnt[b];
    if (cnt > CAND_CAP) cnt = CAND_CAP;
    unsigned thresh = s_thresh;
    for (unsigned i = tid; i < cnt; i += blockDim.x) {
        unsigned long long key = g_cand[b * CAND_CAP + i];
        if ((unsigned)(key >> 32) >= thresh) {
            unsigned pos = atomicAdd(&s_n, 1u);
            if (pos < SBUF) s_cand[pos] = key;
        }
    }
    __syncthreads();

    // Bitonic sort descending over SBUF elements
    for (int k = 2; k <= SBUF; k <<= 1) {
        for (int j = k >> 1; j > 0; j >>= 1) {
            for (int i = tid; i < SBUF; i += blockDim.x) {
                int ixj = i ^ j;
                if (ixj > i) {
                    unsigned long long a = s_cand[i];
                    unsigned long long c = s_cand[ixj];
                    bool descHalf = ((i & k) == 0);
                    if (descHalf ? (a < c) : (a > c)) {
                        s_cand[i]   = c;
                        s_cand[ixj] = a;
                    }
                }
            }
            __syncthreads();
        }
    }

    // Decode top-K: coors / scores / mask
    if (tid < K_TOP) {
        unsigned long long key = s_cand[tid];
        unsigned bits  = (unsigned)(key >> 32);
        float    score = __uint_as_float(bits);
        int yv = 0, xv = 0, valid = 0;
        if (score > 0.5f) {
            unsigned idx = ~((unsigned)key);   // batch-local pixel index
            yv = (int)(idx / W);
            xv = (int)(idx - (unsigned)yv * W);
            valid = 1;
        } else {
            score = 0.0f;
        }
        s_y[tid] = yv; s_x[tid] = xv; s_valid[tid] = valid;

        int bk = b * K_TOP + tid;
        out[OFF_COORS  + bk * 2 + 0] = (float)yv;
        out[OFF_COORS  + bk * 2 + 1] = (float)xv;
        out[OFF_SCORES + bk]         = score;
        out[OFF_MASK   + bk]         = valid ? 1.0f : 0.0f;
    }
    __syncthreads();

    // Params gather: 100 rows x 64 floats = 1600 float4 per batch
    const float4* pms4 = (const float4*)pms;
    float4*       out4 = (float4*)(out + OFF_PARAMS);
    for (int e = tid; e < K_TOP * (P / 4); e += blockDim.x) {
        int k = e >> 4;       // /16 float4 per row
        int c = e & 15;
        float4 v = make_float4(0.f, 0.f, 0.f, 0.f);
        if (s_valid[k]) {
            long long rowOff =
                ((long long)(b * H + s_y[k]) * W + s_x[k]) * (P / 4);
            v = pms4[rowOff + c];
        }
        out4[(long long)(b * K_TOP + k) * (P / 4) + c] = v;
    }
}

// ---------------------------------------------------------------------------
extern "C" void kernel_launch(void* const* d_in, const int* in_sizes, int n_in,
                              void* d_out, int out_size) {
    const float* hms = (const float*)d_in[0];
    const float* pms = (const float*)d_in[1];
    float* out = (float*)d_out;

    k0_zero<<<64, 256>>>();
    k1_peaks<<<(B * HW) / 256, 256>>>(hms);
    k2_select<<<B, 256>>>(pms, out);
}

// round 2
// speedup vs baseline: 1.2153x; 1.2153x over previous
#include <cuda_runtime.h>
#include <cuda_bf16.h>
#include <float.h>
#include <stdint.h>

// Problem constants
#define B        16
#define H        320
#define W        320
#define HW       (H * W)          // 102400
#define P        64
#define K_TOP    100
#define NBINS    1024
#define CAND_CAP 32768            // per-batch global candidate capacity
#define SBUF     512              // shared sort buffer (power of 2)
#define TR       8                // rows per K1 block

// Output layout (float32, concatenated in reference tuple order):
//   coors  [B,K,2]  -> 0      (3200)
//   params [B,K,64] -> 3200   (102400)
//   scores [B,K]    -> 105600 (1600)
//   mask   [B,K]    -> 107200 (1600)
#define OFF_COORS  0
#define OFF_PARAMS 3200
#define OFF_SCORES 105600
#define OFF_MASK   107200

// Device scratch (zero-initialized at module load; K2 re-zeros hist/cnt after
// use, so every invocation both starts and ends with zeros -> graph-replay safe)
__device__ unsigned           g_hist[B * NBINS];
__device__ unsigned           g_cnt[B];
__device__ unsigned long long g_cand[B * CAND_CAP];

// ---------------------------------------------------------------------------
// K1: tiled 3x3 peak NMS + candidate collection.
// Grid: (H/TR, B). Block: 256 threads handles TR rows x 320 cols of one image.
// ---------------------------------------------------------------------------
__global__ __launch_bounds__(256) void k1_peaks(const float* __restrict__ hms) {
    __shared__ float s_tile[(TR + 2) * W];   // rows y0-1 .. y0+TR
    __shared__ float s_cmax[TR * W];         // vertical 3-max per output row

    const int b   = blockIdx.y;
    const int y0  = blockIdx.x * TR;
    const int tid = threadIdx.x;
    const int lane = tid & 31;

    const float* hb = hms + b * HW;

    // ---- Load (TR+2) rows as float4; OOB rows filled with -inf ----
    // (TR+2)*W/4 = 800 float4 loads, 256 threads
    for (int i = tid; i < (TR + 2) * (W / 4); i += 256) {
        int r  = i / (W / 4);          // tile row 0..TR+1
        int c4 = i - r * (W / 4);
        int gy = y0 - 1 + r;
        float4 v;
        if (gy >= 0 && gy < H) {
            v = ((const float4*)(hb + gy * W))[c4];
        } else {
            v = make_float4(-FLT_MAX, -FLT_MAX, -FLT_MAX, -FLT_MAX);
        }
        ((float4*)s_tile)[i] = v;
    }
    __syncthreads();

    // ---- Phase A: column max over 3 vertical neighbors ----
    for (int i = tid; i < TR * W; i += 256) {
        int r = i / W;                 // output row 0..TR-1 (tile row r+1)
        int x = i - r * W;
        float a = s_tile[(r    ) * W + x];
        float c = s_tile[(r + 1) * W + x];
        float d = s_tile[(r + 2) * W + x];
        s_cmax[i] = fmaxf(fmaxf(a, c), d);
    }
    __syncthreads();

    // ---- Phase B: horizontal 3-max, peak test, candidate emission ----
    for (int i = tid; i < TR * W; i += 256) {
        int r = i / W;
        int x = i - r * W;
        float mid = s_tile[(r + 1) * W + x];

        bool isCand = false;
        unsigned bits = 0;
        if (mid > 0.5f) {
            int xl = (x > 0)     ? x - 1 : x;
            int xr = (x < W - 1) ? x + 1 : x;
            float wmax = fmaxf(fmaxf(s_cmax[r * W + xl], s_cmax[r * W + x]),
                               s_cmax[r * W + xr]);
            isCand = (mid >= wmax);
            bits = __float_as_uint(mid);
        }

        unsigned ballot = __ballot_sync(0xffffffffu, isCand);
        if (ballot) {
            int leader = __ffs(ballot) - 1;
            unsigned base = 0;
            if (lane == leader)
                base = atomicAdd(&g_cnt[b], (unsigned)__popc(ballot));
            base = __shfl_sync(0xffffffffu, base, leader);
            if (isCand) {
                unsigned bin;
                if (bits >= 0x3F800000u) bin = NBINS - 1;      // clamp
                else                     bin = (bits - 0x3F000000u) >> 13;
                atomicAdd(&g_hist[b * NBINS + bin], 1u);

                unsigned off = base + (unsigned)__popc(ballot & ((1u << lane) - 1u));
                if (off < CAND_CAP) {
                    unsigned pixIdx = (unsigned)((y0 + r) * W + x);
                    g_cand[b * CAND_CAP + off] =
                        ((unsigned long long)bits << 32) | (unsigned)(~pixIdx);
                }
            }
        }
    }
}

// ---------------------------------------------------------------------------
// K2: per batch — histogram cutoff, filter, bitonic sort (512), decode,
// params gather, and scratch reset. One block of 256 threads per batch.
// ---------------------------------------------------------------------------
__global__ __launch_bounds__(256) void k2_select(const float* __restrict__ pms,
                                                 float* __restrict__ out) {
    __shared__ unsigned long long s_cand[SBUF];
    __shared__ unsigned s_n;
    __shared__ unsigned s_thresh;
    __shared__ int s_y[K_TOP];
    __shared__ int s_x[K_TOP];
    __shared__ int s_valid[K_TOP];

    const int b   = blockIdx.x;
    const int tid = threadIdx.x;

    for (int i = tid; i < SBUF; i += 256) s_cand[i] = 0ull;
    if (tid == 0) {
        s_n = 0;
        unsigned acc = 0;
        int cut = 0;
        for (int bin = NBINS - 1; bin >= 0; --bin) {
            acc += g_hist[b * NBINS + bin];
            if (acc >= K_TOP) { cut = bin; break; }
        }
        s_thresh = 0x3F000000u + ((unsigned)cut << 13);
    }
    __syncthreads();

    // Filter candidate list into shared
    unsigned cnt = g_cnt[b];
    if (cnt > CAND_CAP) cnt = CAND_CAP;
    const unsigned thresh = s_thresh;
    for (unsigned i = tid; i < cnt; i += 256) {
        unsigned long long key = g_cand[b * CAND_CAP + i];
        if ((unsigned)(key >> 32) >= thresh) {
            unsigned pos = atomicAdd(&s_n, 1u);
            if (pos < SBUF) s_cand[pos] = key;
        }
    }
    __syncthreads();

    // Bitonic sort descending, SBUF=512 elements, 256 threads (2 pairs each)
    for (int k = 2; k <= SBUF; k <<= 1) {
        for (int j = k >> 1; j > 0; j >>= 1) {
            for (int i = tid; i < SBUF; i += 256) {
                int ixj = i ^ j;
                if (ixj > i) {
                    unsigned long long a = s_cand[i];
                    unsigned long long c = s_cand[ixj];
                    bool descHalf = ((i & k) == 0);
                    if (descHalf ? (a < c) : (a > c)) {
                        s_cand[i]   = c;
                        s_cand[ixj] = a;
                    }
                }
            }
            __syncthreads();
        }
    }

    // Decode top-K: coors / scores / mask
    if (tid < K_TOP) {
        unsigned long long key = s_cand[tid];
        unsigned bits  = (unsigned)(key >> 32);
        float    score = __uint_as_float(bits);
        int yv = 0, xv = 0, valid = 0;
        if (score > 0.5f) {
            unsigned idx = ~((unsigned)key);
            yv = (int)(idx / W);
            xv = (int)(idx - (unsigned)yv * W);
            valid = 1;
        } else {
            score = 0.0f;
        }
        s_y[tid] = yv; s_x[tid] = xv; s_valid[tid] = valid;

        int bk = b * K_TOP + tid;
        out[OFF_COORS  + bk * 2 + 0] = (float)yv;
        out[OFF_COORS  + bk * 2 + 1] = (float)xv;
        out[OFF_SCORES + bk]         = score;
        out[OFF_MASK   + bk]         = valid ? 1.0f : 0.0f;
    }

    // Reset scratch for the next graph replay (overlaps gather nicely)
    for (int i = tid; i < NBINS; i += 256) g_hist[b * NBINS + i] = 0u;
    if (tid == 0) g_cnt[b] = 0u;
    __syncthreads();

    // Params gather: 100 rows x 16 float4 per batch
    const float4* pms4 = (const float4*)pms;
    float4*       out4 = (float4*)(out + OFF_PARAMS);
    for (int e = tid; e < K_TOP * (P / 4); e += 256) {
        int k = e >> 4;
        int c = e & 15;
        float4 v = make_float4(0.f, 0.f, 0.f, 0.f);
        if (s_valid[k]) {
            long long rowOff =
                ((long long)(b * H + s_y[k]) * W + s_x[k]) * (P / 4);
            v = pms4[rowOff + c];
        }
        out4[(long long)(b * K_TOP + k) * (P / 4) + c] = v;
    }
}

// ---------------------------------------------------------------------------
extern "C" void kernel_launch(void* const* d_in, const int* in_sizes, int n_in,
                              void* d_out, int out_size) {
    const float* hms = (const float*)d_in[0];
    const float* pms = (const float*)d_in[1];
    float* out = (float*)d_out;

    dim3 g1(H / TR, B);
    k1_peaks<<<g1, 256>>>(hms);
    k2_select<<<B, 256>>>(pms, out);
}

// round 3
// speedup vs baseline: 3.2048x; 2.6370x over previous
#include <cuda_runtime.h>
#include <cuda_bf16.h>
#include <float.h>
#include <stdint.h>

#define B        16
#define H        320
#define W        320
#define HW       (H * W)
#define P        64
#define K_TOP    100
#define NBINS    1024
#define CAND_CAP 32768
#define SBUF     512        // K2 survivor cap
#define LBUF     1024       // K1 per-block candidate cap
#define TR       8          // rows per K1 block

// Output layout (float32, tuple order): coors | params | scores | mask
#define OFF_COORS  0
#define OFF_PARAMS 3200
#define OFF_SCORES 105600
#define OFF_MASK   107200

// Device scratch. g_cnt is zeroed at end of K2 each run (zero-init at load).
__device__ unsigned           g_cnt[B];
__device__ unsigned long long g_cand[B * CAND_CAP];

static __device__ __forceinline__ float fmax3(float a, float b, float c) {
    return fmaxf(fmaxf(a, b), c);
}

// ---------------------------------------------------------------------------
// K1: tiled 3x3 peak NMS + block-aggregated candidate emission.
// Grid (H/TR, B), 256 threads.
// ---------------------------------------------------------------------------
__global__ __launch_bounds__(256) void k1_peaks(const float* __restrict__ hms) {
    __shared__ float s_tile[(TR + 2) * W];       // 12.8 KB
    __shared__ float s_cmax[TR * W];             // 10.2 KB
    __shared__ unsigned long long s_buf[LBUF];   // 8 KB
    __shared__ unsigned s_cnt, s_base;

    const int b   = blockIdx.y;
    const int y0  = blockIdx.x * TR;
    const int tid = threadIdx.x;
    const float* hb = hms + b * HW;

    if (tid == 0) s_cnt = 0;

    // ---- Load (TR+2) rows as float4 (800 loads), OOB rows = -inf ----
    #pragma unroll
    for (int u = 0; u < 4; u++) {
        int i = tid + u * 256;
        if (i < (TR + 2) * (W / 4)) {
            int r  = i / (W / 4);
            int gy = y0 - 1 + r;
            float4 v = make_float4(-FLT_MAX, -FLT_MAX, -FLT_MAX, -FLT_MAX);
            if (gy >= 0 && gy < H)
                v = ((const float4*)(hb + gy * W))[i - r * (W / 4)];
            ((float4*)s_tile)[i] = v;
        }
    }
    __syncthreads();

    // ---- Phase A: vertical 3-max (float4) ----
    #pragma unroll
    for (int u = 0; u < 3; u++) {
        int i = tid + u * 256;                 // 0 .. 639 (TR*W/4)
        if (i < TR * (W / 4)) {
            int r  = i / (W / 4);
            int c4 = i - r * (W / 4);
            float4 a = ((const float4*)s_tile)[(r    ) * (W / 4) + c4];
            float4 m = ((const float4*)s_tile)[(r + 1) * (W / 4) + c4];
            float4 d = ((const float4*)s_tile)[(r + 2) * (W / 4) + c4];
            float4 o;
            o.x = fmax3(a.x, m.x, d.x);
            o.y = fmax3(a.y, m.y, d.y);
            o.z = fmax3(a.z, m.z, d.z);
            o.w = fmax3(a.w, m.w, d.w);
            ((float4*)s_cmax)[i] = o;
        }
    }
    __syncthreads();

    // ---- Phase B: horizontal 3-max, peak test, smem compaction ----
    #pragma unroll
    for (int u = 0; u < 3; u++) {
        int i = tid + u * 256;
        if (i < TR * (W / 4)) {
            int r  = i / (W / 4);
            int c4 = i - r * (W / 4);
            int x0 = c4 * 4;
            float4 mid = ((const float4*)s_tile)[(r + 1) * (W / 4) + c4];
            float4 cm  = ((const float4*)s_cmax)[r * (W / 4) + c4];
            float lf = (c4 > 0)          ? s_cmax[r * W + x0 - 1] : cm.x;
            float rt = (c4 < W / 4 - 1)  ? s_cmax[r * W + x0 + 4] : cm.w;

            float wm[4];
            wm[0] = fmax3(lf,   cm.x, cm.y);
            wm[1] = fmax3(cm.x, cm.y, cm.z);
            wm[2] = fmax3(cm.y, cm.z, cm.w);
            wm[3] = fmax3(cm.z, cm.w, rt);
            float mv[4] = {mid.x, mid.y, mid.z, mid.w};

            #pragma unroll
            for (int e = 0; e < 4; e++) {
                if (mv[e] > 0.5f && mv[e] >= wm[e]) {
                    unsigned pos = atomicAdd(&s_cnt, 1u);
                    if (pos < LBUF) {
                        unsigned bits   = __float_as_uint(mv[e]);
                        unsigned pixIdx = (unsigned)((y0 + r) * W + x0 + e);
                        s_buf[pos] = ((unsigned long long)bits << 32)
                                   | (unsigned)(~pixIdx);
                    }
                }
            }
        }
    }
    __syncthreads();

    // ---- One global atomic per block, then coalesced flush ----
    unsigned n = s_cnt;
    if (n > LBUF) n = LBUF;
    if (tid == 0) s_base = atomicAdd(&g_cnt[b], n);
    __syncthreads();
    unsigned base = s_base;
    unsigned long long* dst = g_cand + (size_t)b * CAND_CAP;
    for (unsigned i = tid; i < n; i += 256) {
        unsigned o = base + i;
        if (o < CAND_CAP) dst[o] = s_buf[i];
    }
}

// ---------------------------------------------------------------------------
// K2: per batch — smem histogram, cutoff, filter, rank, decode, gather.
// Grid B, 256 threads.
// ---------------------------------------------------------------------------
__global__ __launch_bounds__(256) void k2_select(const float* __restrict__ pms,
                                                 float* __restrict__ out) {
    __shared__ unsigned s_hist[NBINS];
    __shared__ unsigned s_chunk[256];
    __shared__ unsigned long long s_cand[SBUF];
    __shared__ unsigned s_n, s_thresh;
    __shared__ float s_score[K_TOP];
    __shared__ int   s_y[K_TOP], s_x[K_TOP], s_valid[K_TOP];

    const int b   = blockIdx.x;
    const int tid = threadIdx.x;
    const unsigned long long* cand = g_cand + (size_t)b * CAND_CAP;

    #pragma unroll
    for (int u = 0; u < 4; u++) s_hist[tid + u * 256] = 0u;
    if (tid < K_TOP) { s_valid[tid] = 0; s_y[tid] = 0; s_x[tid] = 0; s_score[tid] = 0.f; }
    if (tid == 0) s_n = 0;

    unsigned cnt = g_cnt[b];
    if (cnt > CAND_CAP) cnt = CAND_CAP;
    __syncthreads();

    // ---- Pass 1: histogram of score bits (MLP-8 batched loads) ----
    for (unsigned base = 0; base < cnt; base += 256 * 8) {
        unsigned long long v[8];
        #pragma unroll
        for (int u = 0; u < 8; u++) {
            unsigned i = base + u * 256 + tid;
            v[u] = (i < cnt) ? cand[i] : 0ull;
        }
        #pragma unroll
        for (int u = 0; u < 8; u++) {
            if (v[u]) {
                unsigned bits = (unsigned)(v[u] >> 32);
                unsigned bin  = (bits >= 0x3F800000u) ? (NBINS - 1)
                                                      : ((bits - 0x3F000000u) >> 13);
                atomicAdd(&s_hist[bin], 1u);
            }
        }
    }
    __syncthreads();

    // ---- Cutoff: chunked suffix scan (256 chunks of 4 bins) ----
    {
        unsigned c0 = s_hist[tid * 4 + 0] + s_hist[tid * 4 + 1]
                    + s_hist[tid * 4 + 2] + s_hist[tid * 4 + 3];
        s_chunk[tid] = c0;
    }
    __syncthreads();
    if (tid == 0) {
        unsigned acc = 0;
        int cut = 0;
        for (int ch = 255; ch >= 0; --ch) {
            unsigned c = s_chunk[ch];
            if (acc + c >= K_TOP) {
                for (int bin = ch * 4 + 3; bin >= ch * 4; --bin) {
                    acc += s_hist[bin];
                    if (acc >= K_TOP) { cut = bin; break; }
                }
                if (acc < K_TOP) cut = ch * 4;   // unreachable safety
                break;
            }
            acc += c;
        }
        s_thresh = 0x3F000000u + ((unsigned)cut << 13);
    }
    __syncthreads();

    // ---- Pass 2: filter into shared (MLP-8 batched) ----
    const unsigned thresh = s_thresh;
    for (unsigned base = 0; base < cnt; base += 256 * 8) {
        unsigned long long v[8];
        #pragma unroll
        for (int u = 0; u < 8; u++) {
            unsigned i = base + u * 256 + tid;
            v[u] = (i < cnt) ? cand[i] : 0ull;
        }
        #pragma unroll
        for (int u = 0; u < 8; u++) {
            if (v[u] && (unsigned)(v[u] >> 32) >= thresh) {
                unsigned pos = atomicAdd(&s_n, 1u);
                if (pos < SBUF) s_cand[pos] = v[u];
            }
        }
    }
    __syncthreads();

    // ---- Rank by counting (keys unique); fill top-K slots ----
    unsigned n = s_n;
    if (n > SBUF) n = SBUF;
    for (unsigned c = tid; c < n; c += 256) {
        unsigned long long key = s_cand[c];
        unsigned rank = 0;
        for (unsigned j = 0; j < n; j++) rank += (s_cand[j] > key);
        if (rank < K_TOP) {
            unsigned bits = (unsigned)(key >> 32);
            unsigned idx  = ~((unsigned)key);
            int yv = (int)(idx / W);
            int xv = (int)(idx - (unsigned)yv * W);
            s_score[rank] = __uint_as_float(bits);
            s_y[rank] = yv;
            s_x[rank] = xv;
            s_valid[rank] = 1;
        }
    }
    __syncthreads();

    // ---- coors / scores / mask ----
    if (tid < K_TOP) {
        int v = s_valid[tid];
        int bk = b * K_TOP + tid;
        out[OFF_COORS  + bk * 2 + 0] = (float)s_y[tid];
        out[OFF_COORS  + bk * 2 + 1] = (float)s_x[tid];
        out[OFF_SCORES + bk]         = v ? s_score[tid] : 0.0f;
        out[OFF_MASK   + bk]         = v ? 1.0f : 0.0f;
    }
    if (tid == 0) g_cnt[b] = 0u;   // reset for next replay

    // ---- Params gather: 1600 float4 per batch, MLP-7 ----
    const float4* pms4 = (const float4*)pms;
    float4*       out4 = (float4*)(out + OFF_PARAMS);
    float4 vals[7];
    #pragma unroll
    for (int u = 0; u < 7; u++) {
        int e = tid + u * 256;
        vals[u] = make_float4(0.f, 0.f, 0.f, 0.f);
        if (e < K_TOP * (P / 4)) {
            int k = e >> 4;
            int c = e & 15;
            if (s_valid[k]) {
                long long rowOff = ((long long)(b * H + s_y[k]) * W + s_x[k]) * (P / 4);
                vals[u] = pms4[rowOff + c];
            }
        }
    }
    #pragma unroll
    for (int u = 0; u < 7; u++) {
        int e = tid + u * 256;
        if (e < K_TOP * (P / 4)) {
            int k = e >> 4;
            int c = e & 15;
            out4[(long long)(b * K_TOP + k) * (P / 4) + c] = vals[u];
        }
    }
}

// ---------------------------------------------------------------------------
extern "C" void kernel_launch(void* const* d_in, const int* in_sizes, int n_in,
                              void* d_out, int out_size) {
    const float* hms = (const float*)d_in[0];
    const float* pms = (const float*)d_in[1];
    float* out = (float*)d_out;

    dim3 g1(H / TR, B);
    k1_peaks<<<g1, 256>>>(hms);
    k2_select<<<B, 256>>>(pms, out);
}